// round 1
// baseline (speedup 1.0000x reference)
#include <cuda_runtime.h>
#include <math_constants.h>

#define BB 8
#define CC 128
#define NN 65536
#define SS 100
#define CHUNKS 54
#define CHUNK_PTS 1216      // multiple of 32; 54*1216 = 65664 >= 65536
#define ACC_ROWS 101        // +1 dummy row for invalid labels
#define THREADS 128
#define SMEM_BYTES ((ACC_ROWS * CC + 4 * 1024) * 4)   // 68,096 B

__device__ int g_is64;
__device__ float g_partial[(long long)BB * CHUNKS * SS * CC];  // ~22.1 MB scratch

// Detect whether labels are int64 (JAX x64 on) or int32 (x64 off downcast).
// int64 little-endian => every odd 32-bit word of the first 64 labels is 0.
__global__ void detect_kernel(const unsigned* __restrict__ lab) {
    int is64 = 1;
    for (int i = 0; i < 64; ++i)
        if (lab[2 * i + 1] != 0u) { is64 = 0; break; }
    g_is64 = is64;
}

extern "C" __global__ void __launch_bounds__(THREADS, 3)
seg_max_partial(const float* __restrict__ pf, const void* __restrict__ labels_raw) {
    extern __shared__ float smem[];
    float* acc = smem;                        // [ACC_ROWS][CC]
    float* tiles = smem + ACC_ROWS * CC;      // 4 warps x 32c x 32n

    const int tid  = threadIdx.x;
    const int lane = tid & 31;
    const int w    = tid >> 5;
    const int b     = blockIdx.x / CHUNKS;
    const int chunk = blockIdx.x % CHUNKS;
    const int c0 = w * 32;                    // warp-exclusive feature columns
    float* tile = tiles + w * 1024;

    for (int i = tid; i < ACC_ROWS * CC; i += THREADS) acc[i] = -CUDART_INF_F;
    __syncthreads();

    const int is64 = g_is64;
    const long long* lab64 = (const long long*)labels_raw;
    const int*       lab32 = (const int*)labels_raw;

    const int n_start = chunk * CHUNK_PTS;
    const int n_end = min(n_start + CHUNK_PTS, NN);
    const float* pf_b = pf + (long long)b * CC * NN;
    const long long lab_base = (long long)b * NN;

    if (n_start < n_end) {
        float4 r[8];
        int l;
        // prefetch first tile
        {
            const int n0 = n_start;
            long long li = is64 ? lab64[lab_base + n0 + lane]
                                : (long long)lab32[lab_base + n0 + lane];
            l = (int)li;
            if (l < 0 || l >= SS) l = SS;
#pragma unroll
            for (int k = 0; k < 8; ++k) {
                int cc = k * 4 + (lane >> 3);
                int nn = (lane & 7) * 4;
                r[k] = *(const float4*)(pf_b + (long long)(c0 + cc) * NN + n0 + nn);
            }
        }
        for (int n0 = n_start; n0 < n_end; n0 += 32) {
            __syncwarp();   // previous tile reads complete before overwrite
#pragma unroll
            for (int k = 0; k < 8; ++k) {
                int cc = k * 4 + (lane >> 3);
                int nn = (lane & 7) * 4;
                *(float4*)(tile + cc * 32 + nn) = r[k];   // phase-conflict-free STS.128
            }
            const int lcur = l;
            __syncwarp();   // tile visible to all lanes

            // prefetch next tile while accumulating this one
            const int n1 = n0 + 32;
            if (n1 < n_end) {
                long long li = is64 ? lab64[lab_base + n1 + lane]
                                    : (long long)lab32[lab_base + n1 + lane];
                l = (int)li;
                if (l < 0 || l >= SS) l = SS;
#pragma unroll
                for (int k = 0; k < 8; ++k) {
                    int cc = k * 4 + (lane >> 3);
                    int nn = (lane & 7) * 4;
                    r[k] = *(const float4*)(pf_b + (long long)(c0 + cc) * NN + n1 + nn);
                }
            }

            // Diagonal stagger: step j -> lane handles column (lane+j)&31.
            // All lanes hit distinct columns each step => race-free non-atomic
            // RMW, and bank = c mod 32 => conflict-free LDS/STS.
            float* arow = acc + lcur * CC + c0;
#pragma unroll
            for (int j = 0; j < 32; ++j) {
                int cl = (lane + j) & 31;
                float v = tile[cl * 32 + lane];
                arow[cl] = fmaxf(arow[cl], v);
            }
        }
    }
    __syncthreads();

    // write per-block partial (rows 0..SS-1; dummy row dropped)
    float* dst = g_partial + (long long)blockIdx.x * (SS * CC);
    for (int i = tid; i < SS * CC; i += THREADS) dst[i] = acc[i];
}

__global__ void seg_max_reduce(float* __restrict__ out) {
    int idx = blockIdx.x * blockDim.x + threadIdx.x;   // over BB*SS*CC
    if (idx >= BB * SS * CC) return;
    int b  = idx / (SS * CC);
    int rc = idx % (SS * CC);
    const float* src = g_partial + ((long long)b * CHUNKS) * (SS * CC) + rc;
    float m = -CUDART_INF_F;
#pragma unroll 1
    for (int k = 0; k < CHUNKS; ++k)
        m = fmaxf(m, src[(long long)k * (SS * CC)]);
    out[idx] = m;
}

extern "C" void kernel_launch(void* const* d_in, const int* in_sizes, int n_in,
                              void* d_out, int out_size) {
    const float* pf     = (const float*)d_in[0];
    const void*  labels = d_in[2];               // d_in[1] (points) unused
    float* out = (float*)d_out;

    cudaFuncSetAttribute(seg_max_partial,
                         cudaFuncAttributeMaxDynamicSharedMemorySize, SMEM_BYTES);

    detect_kernel<<<1, 1>>>((const unsigned*)labels);
    seg_max_partial<<<BB * CHUNKS, THREADS, SMEM_BYTES>>>(pf, labels);
    seg_max_reduce<<<(BB * SS * CC + 255) / 256, 256>>>(out);
}

// round 2
// speedup vs baseline: 1.0754x; 1.0754x over previous
#include <cuda_runtime.h>
#include <math_constants.h>

#define BB 8
#define CC 128
#define NN 65536
#define SS 100
#define CHUNKS 54
#define CHUNK_PTS 1216      // multiple of 64; 54*1216 = 65664 >= 65536
#define ACC_ROWS 101        // +1 dummy row for invalid labels
#define THREADS 128
#define SMEM_BYTES ((ACC_ROWS * CC + 4 * 1024) * 4)   // 68,096 B

__device__ float g_partial[(long long)BB * CHUNKS * SS * CC];  // ~22.1 MB scratch

// ---- helpers ------------------------------------------------------------

__device__ __forceinline__ void load_tile(float4 (&r)[8], int& l,
                                          const float* __restrict__ pf_b,
                                          const void* __restrict__ labels,
                                          long long lab_base, int n0,
                                          int lane, int c0, int is64) {
    long long li = is64 ? ((const long long*)labels)[lab_base + n0 + lane]
                        : (long long)((const int*)labels)[lab_base + n0 + lane];
    int ll = (int)li;
    if (ll < 0 || ll >= SS) ll = SS;
    l = ll;
#pragma unroll
    for (int k = 0; k < 8; ++k) {
        int cc = k * 4 + (lane >> 3);
        int nn = (lane & 7) * 4;
        r[k] = *(const float4*)(pf_b + (long long)(c0 + cc) * NN + n0 + nn);
    }
}

__device__ __forceinline__ void store_tile(float* __restrict__ tile,
                                           const float4 (&r)[8], int lane) {
#pragma unroll
    for (int k = 0; k < 8; ++k) {
        int cc = k * 4 + (lane >> 3);
        int nn = (lane & 7) * 4;
        *(float4*)(tile + cc * 32 + nn) = r[k];   // phase-conflict-free STS.128
    }
}

// Diagonal stagger: at step j, lane handles column (lane+j)&31 -> all 32 lanes
// on distinct columns every step => race-free non-atomic RMW, zero bank
// conflicts on both tile (bank=lane) and acc (bank=cl).
__device__ __forceinline__ void accumulate(float* __restrict__ acc,
                                           const float* __restrict__ tile,
                                           int l, int lane, int c0) {
    float* arow = acc + l * CC + c0;
#pragma unroll
    for (int j = 0; j < 32; ++j) {
        int cl = (lane + j) & 31;
        float v = tile[cl * 32 + lane];
        arow[cl] = fmaxf(arow[cl], v);
    }
}

// ---- main kernel --------------------------------------------------------

extern "C" __global__ void __launch_bounds__(THREADS, 3)
seg_max_partial(const float* __restrict__ pf, const void* __restrict__ labels_raw) {
    __shared__ int s_is64;
    extern __shared__ float smem[];
    float* acc = smem;                        // [ACC_ROWS][CC]
    float* tiles = smem + ACC_ROWS * CC;      // 4 warps x 32c x 32n
    const int tid  = threadIdx.x;
    const int lane = tid & 31;
    const int w    = tid >> 5;
    const int b     = blockIdx.x / CHUNKS;
    const int chunk = blockIdx.x % CHUNKS;
    const int c0 = w * 32;                    // warp-exclusive feature columns
    float* tile = tiles + w * 1024;

    // Inline label-width detection: int64 LE => first 64 odd words all zero.
    if (tid == 0) s_is64 = 1;
    __syncthreads();
    if (tid < 64) {
        const unsigned* u = (const unsigned*)labels_raw;
        if (u[2 * tid + 1] != 0u) s_is64 = 0;
    }
    // vectorized acc init (ACC_ROWS*CC = 12928, divisible by 4)
    const float4 ninf4 = make_float4(-CUDART_INF_F, -CUDART_INF_F,
                                     -CUDART_INF_F, -CUDART_INF_F);
    for (int i = tid; i < ACC_ROWS * CC / 4; i += THREADS) ((float4*)acc)[i] = ninf4;
    __syncthreads();
    const int is64 = s_is64;

    const int n_start = chunk * CHUNK_PTS;
    const int n_end = min(n_start + CHUNK_PTS, NN);
    const float* pf_b = pf + (long long)b * CC * NN;
    const long long lab_base = (long long)b * NN;

    if (n_start < n_end) {
        float4 rA[8], rB[8];
        int lA = SS, lB = SS;
        // prologue: preload two tiles
        load_tile(rA, lA, pf_b, labels_raw, lab_base, n_start, lane, c0, is64);
        if (n_start + 32 < n_end)
            load_tile(rB, lB, pf_b, labels_raw, lab_base, n_start + 32, lane, c0, is64);

        for (int n0 = n_start; n0 < n_end; n0 += 64) {
            // --- phase A: consume rA (data n0), prefetch rA <- n0+64 ---
            __syncwarp();             // prior tile reads complete before overwrite
            store_tile(tile, rA, lane);
            const int lcurA = lA;
            __syncwarp();             // tile visible to all lanes
            if (n0 + 64 < n_end)
                load_tile(rA, lA, pf_b, labels_raw, lab_base, n0 + 64, lane, c0, is64);
            accumulate(acc, tile, lcurA, lane, c0);

            // --- phase B: consume rB (data n0+32), prefetch rB <- n0+96 ---
            if (n0 + 32 < n_end) {
                __syncwarp();
                store_tile(tile, rB, lane);
                const int lcurB = lB;
                __syncwarp();
                if (n0 + 96 < n_end)
                    load_tile(rB, lB, pf_b, labels_raw, lab_base, n0 + 96, lane, c0, is64);
                accumulate(acc, tile, lcurB, lane, c0);
            }
        }
    }
    __syncthreads();

    // vectorized per-block partial write (dummy row ACC_ROWS-1 dropped)
    float* dst = g_partial + (long long)blockIdx.x * (SS * CC);
    for (int i = tid; i < SS * CC / 4; i += THREADS)
        ((float4*)dst)[i] = ((const float4*)acc)[i];
}

// ---- cross-chunk reduce (float4) ---------------------------------------

__global__ void seg_max_reduce(float* __restrict__ out) {
    const int QC = SS * CC / 4;    // 3200 float4 per (b, chunk) partial
    int idx = blockIdx.x * blockDim.x + threadIdx.x;   // over BB*QC
    if (idx >= BB * QC) return;
    int b  = idx / QC;
    int rc = idx % QC;
    const float4* src = (const float4*)g_partial + (long long)b * CHUNKS * QC + rc;
    float4 m = src[0];
#pragma unroll 6
    for (int k = 1; k < CHUNKS; ++k) {
        float4 v = src[(long long)k * QC];
        m.x = fmaxf(m.x, v.x);
        m.y = fmaxf(m.y, v.y);
        m.z = fmaxf(m.z, v.z);
        m.w = fmaxf(m.w, v.w);
    }
    ((float4*)out)[idx] = m;
}

extern "C" void kernel_launch(void* const* d_in, const int* in_sizes, int n_in,
                              void* d_out, int out_size) {
    const float* pf     = (const float*)d_in[0];
    const void*  labels = d_in[2];               // d_in[1] (points) unused
    float* out = (float*)d_out;

    cudaFuncSetAttribute(seg_max_partial,
                         cudaFuncAttributeMaxDynamicSharedMemorySize, SMEM_BYTES);

    seg_max_partial<<<BB * CHUNKS, THREADS, SMEM_BYTES>>>(pf, labels);
    const int QC = SS * CC / 4;
    seg_max_reduce<<<(BB * QC + 255) / 256, 256>>>(out);
}